// round 12
// baseline (speedup 1.0000x reference)
#include <cuda_runtime.h>
#include <math.h>
#include <cstdint>
#include <float.h>

#define G        16
#define NCM      (G * G * G)        // 4096 model cells
#define GP       8
#define NCP      (GP * GP * GP)     // 512 pred cells
#define THREADS  512
#define NWARP    16
#define MAXM     16384
#define MAXP     32768
#define BUFPTS   10240              // staging buffer capacity (points)
#define TARGETPTS 48

// -------- device scratch (static; no allocations) --------
__device__ float4 g_pu[MAXP];      // unsorted preds (px,py,pz,a)
__device__ float  g_puw[MAXP];     // unsorted pred weights
__device__ float4 g_ps[MAXP];      // cell-sorted preds
__device__ float  g_wt[MAXP];      // cell-sorted weights
__device__ float4 g_ms[MAXM];      // cell-sorted model (x,y,z,|g|^2)
__device__ int g_mhist[NCM], g_mcur[NCM];   // zero; reset each launch
__device__ int g_phist[NCP], g_pcur[NCP];   // zero; reset each launch
__device__ int g_bbmin[3] = {0x7fffffff, 0x7fffffff, 0x7fffffff};
__device__ int g_bbmax[3] = {(int)0x80000000, (int)0x80000000, (int)0x80000000};
__device__ float g_partials[NCP];
__device__ unsigned int g_bar1, g_bar2, g_bar3, g_wq, g_ticket;

// dynamic smem layout (bytes)
#define OFF_MSTART   0                       // (NCM+1) ints
#define OFF_PSTART   16400                   // (NCP+1) ints
#define OFF_SEGSTART 18464                   // 256 ints
#define OFF_SEGOFF   19488                   // 257 ints
#define OFF_SMIN     20528                   // NWARP*128 floats
#define OFF_BUF      28736                   // BUFPTS/2 pair records (32B each)
#define SMEM_TOTAL   (OFF_BUF + (BUFPTS / 2) * 32)   // 192576

__device__ __forceinline__ int f2ord(float f) {
    int i = __float_as_int(f);
    return i >= 0 ? i : (i ^ 0x7fffffff);
}
__device__ __forceinline__ float ord2f(int o) {
    return __int_as_float(o >= 0 ? o : (o ^ 0x7fffffff));
}
__device__ __forceinline__ int cellc(float v, float o, float ih, int g) {
    int c = (int)floorf((v - o) * ih);
    return min(max(c, 0), g - 1);
}

__device__ __forceinline__ void grid_bar(unsigned int* ctr, unsigned int tgt) {
    __syncthreads();
    if (threadIdx.x == 0) {
        __threadfence();
        atomicAdd(ctr, 1u);
        while (*((volatile unsigned int*)ctr) < tgt) { }
        __threadfence();
    }
    __syncthreads();
}

// Warp-sliced packed f32x2 min-scan over npairs pair records in s_model.
__device__ __forceinline__ void scan_pairs(const float* s_model, int npairs, int warp,
                                           const uint64_t* qx2, const uint64_t* qy2,
                                           const uint64_t* qz2, float* m_lo, float* m_hi) {
    int ps = (npairs + NWARP - 1) / NWARP;
    int pb = warp * ps; if (pb > npairs) pb = npairs;
    int pe = pb + ps;   if (pe > npairs) pe = npairs;
    uint32_t addr;
    {
        uint64_t a64;
        asm("cvta.to.shared.u64 %0, %1;" : "=l"(a64) : "l"(s_model + (size_t)pb * 8));
        addr = (uint32_t)a64;
    }
    #pragma unroll 4
    for (int p = pb; p < pe; ++p, addr += 32u) {
        uint64_t x2, y2, z2, w2;
        asm("ld.shared.v2.u64 {%0,%1}, [%2];"    : "=l"(x2), "=l"(y2) : "r"(addr));
        asm("ld.shared.v2.u64 {%0,%1}, [%2+16];" : "=l"(z2), "=l"(w2) : "r"(addr));
        #pragma unroll
        for (int k = 0; k < 4; k++) {
            uint64_t d2;
            asm("fma.rn.f32x2 %0, %1, %2, %3;" : "=l"(d2) : "l"(qz2[k]), "l"(z2), "l"(w2));
            asm("fma.rn.f32x2 %0, %1, %2, %0;" : "+l"(d2) : "l"(qy2[k]), "l"(y2));
            asm("fma.rn.f32x2 %0, %1, %2, %0;" : "+l"(d2) : "l"(qx2[k]), "l"(x2));
            float dlo, dhi;
            asm("mov.b64 {%0,%1}, %2;" : "=f"(dlo), "=f"(dhi) : "l"(d2));
            m_lo[k] = fminf(m_lo[k], dlo);
            m_hi[k] = fminf(m_hi[k], dhi);
        }
    }
}

__global__ __launch_bounds__(THREADS, 1)
void cd_kernel(const float* __restrict__ vis,
               const float* __restrict__ tac,
               const float* __restrict__ model,
               const float* __restrict__ scale,
               const float* __restrict__ state,
               float* __restrict__ out,
               int nv, int nt, int nm,
               float wv, float wt) {
    extern __shared__ char smem[];
    int*   s_mstart = (int*)(smem + OFF_MSTART);     // NCM+1
    int*   s_pstart = (int*)(smem + OFF_PSTART);     // NCP+1
    int*   s_segst  = (int*)(smem + OFF_SEGSTART);   // 256
    int*   s_segoff = (int*)(smem + OFF_SEGOFF);     // 257
    float* s_min    = (float*)(smem + OFF_SMIN);     // NWARP*128
    float* s_buf    = (float*)(smem + OFF_BUF);      // pair records

    __shared__ float s_par[13];
    __shared__ float s_geo[9];       // ox,oy,oz, ihx,ihy,ihz (model), ihp xyz (pred)
    __shared__ float s_m1[128];
    __shared__ float s_fb[6];
    __shared__ int s_bx[6];
    __shared__ int s_total, s_nseg, s_cell, s_skip, s_last;

    const int tid  = threadIdx.x;
    const int lane = tid & 31;
    const int warp = tid >> 5;
    const int ntot0 = nv + nt;
    const int ntot = ntot0 < MAXP ? ntot0 : MAXP;
    const int nmm  = nm < MAXM ? nm : MAXM;
    const unsigned int GRID = gridDim.x;
    const int gstride = (int)GRID * THREADS;
    const int gtid = blockIdx.x * THREADS + tid;
    const int target = TARGETPTS < nmm ? TARGETPTS : nmm;

    // ---- transform params ----
    if (tid == 0) {
        float oxs = state[3], oys = state[4], ozs = state[5];
        float sx = sinf(oxs), cx = cosf(oxs);
        float sy = sinf(oys), cy = cosf(oys);
        float sz = sinf(ozs), cz = cosf(ozs);
        s_par[0] = cz * cy;
        s_par[1] = cz * sy * sx - sz * cx;
        s_par[2] = cz * sy * cx + sz * sx;
        s_par[3] = sz * cy;
        s_par[4] = sz * sy * sx + cz * cx;
        s_par[5] = sz * sy * cx - cz * sx;
        s_par[6] = -sy;
        s_par[7] = cy * sx;
        s_par[8] = cy * cx;
        s_par[9]  = state[0];
        s_par[10] = state[1];
        s_par[11] = state[2];
        s_par[12] = 1.0f / scale[0];
    }
    __syncthreads();

    // ============ Phase A: model bbox + pred transform ============
    {
        float bmn[3] = {FLT_MAX, FLT_MAX, FLT_MAX};
        float bmx[3] = {-FLT_MAX, -FLT_MAX, -FLT_MAX};
        for (int j = gtid; j < nmm; j += gstride) {
            float gx = model[3 * j], gy = model[3 * j + 1], gz = model[3 * j + 2];
            bmn[0] = fminf(bmn[0], gx); bmx[0] = fmaxf(bmx[0], gx);
            bmn[1] = fminf(bmn[1], gy); bmx[1] = fmaxf(bmx[1], gy);
            bmn[2] = fminf(bmn[2], gz); bmx[2] = fmaxf(bmx[2], gz);
        }
        for (int i = gtid; i < ntot; i += gstride) {
            const float* src; int idx; float w;
            if (i < nv) { src = vis; idx = i;      w = wv; }
            else        { src = tac; idx = i - nv; w = wt; }
            float vx = src[3 * idx + 0] - s_par[9];
            float vy = src[3 * idx + 1] - s_par[10];
            float vz = src[3 * idx + 2] - s_par[11];
            float inv_s = s_par[12];
            float px = (vx * s_par[0] + vy * s_par[3] + vz * s_par[6]) * inv_s;
            float py = (vx * s_par[1] + vy * s_par[4] + vz * s_par[7]) * inv_s;
            float pz = (vx * s_par[2] + vy * s_par[5] + vz * s_par[8]) * inv_s;
            float a = fmaf(px, px, fmaf(py, py, pz * pz));
            g_pu[i]  = make_float4(px, py, pz, a);
            g_puw[i] = w;
        }
        #pragma unroll
        for (int o = 16; o > 0; o >>= 1)
            #pragma unroll
            for (int d = 0; d < 3; d++) {
                bmn[d] = fminf(bmn[d], __shfl_xor_sync(0xffffffffu, bmn[d], o));
                bmx[d] = fmaxf(bmx[d], __shfl_xor_sync(0xffffffffu, bmx[d], o));
            }
        if (lane == 0) {
            #pragma unroll
            for (int d = 0; d < 3; d++) {
                atomicMin(&g_bbmin[d], f2ord(bmn[d]));
                atomicMax(&g_bbmax[d], f2ord(bmx[d]));
            }
        }
    }
    grid_bar(&g_bar1, GRID);

    // decode grid geometry
    if (tid == 0) {
        #pragma unroll
        for (int d = 0; d < 3; d++) {
            float mn = ord2f(g_bbmin[d]), mx = ord2f(g_bbmax[d]);
            float span = mx - mn;
            float pad = span * 1e-3f + 1e-6f;
            float o = mn - pad, sp = span + 2.0f * pad;
            s_geo[d] = o;
            s_geo[3 + d] = (float)G / sp;
            s_geo[6 + d] = (float)GP / sp;
        }
    }
    __syncthreads();
    const float ox = s_geo[0], oy = s_geo[1], oz = s_geo[2];
    const float ihx = s_geo[3], ihy = s_geo[4], ihz = s_geo[5];
    const float ipx = s_geo[6], ipy = s_geo[7], ipz = s_geo[8];

    // ============ Phase B: cell histograms ============
    for (int j = gtid; j < nmm; j += gstride) {
        float gx = model[3 * j], gy = model[3 * j + 1], gz = model[3 * j + 2];
        int c = (cellc(gx, ox, ihx, G) * G + cellc(gy, oy, ihy, G)) * G + cellc(gz, oz, ihz, G);
        atomicAdd(&g_mhist[c], 1);
    }
    for (int i = gtid; i < ntot; i += gstride) {
        float4 P = g_pu[i];
        int c = (cellc(P.x, ox, ipx, GP) * GP + cellc(P.y, oy, ipy, GP)) * GP + cellc(P.z, oz, ipz, GP);
        atomicAdd(&g_phist[c], 1);
    }
    grid_bar(&g_bar2, GRID);
    if (blockIdx.x == 0 && tid < 3) {                 // reset bbox for replay
        g_bbmin[tid] = 0x7fffffff;
        g_bbmax[tid] = (int)0x80000000;
    }

    // ============ Phase C: local scans + scatter ============
    {
        int* s_ws = (int*)s_buf;
        int loc[8]; int base = tid * 8; int ssum = 0;
        #pragma unroll
        for (int r = 0; r < 8; r++) { loc[r] = g_mhist[base + r]; ssum += loc[r]; }
        s_ws[tid] = ssum;
        __syncthreads();
        for (int off = 1; off < THREADS; off <<= 1) {
            int t = (tid >= off) ? s_ws[tid - off] : 0;
            __syncthreads(); s_ws[tid] += t; __syncthreads();
        }
        int run = s_ws[tid] - ssum;
        #pragma unroll
        for (int r = 0; r < 8; r++) { s_mstart[base + r] = run; run += loc[r]; }
        if (tid == THREADS - 1) s_mstart[NCM] = run;
        __syncthreads();

        int v = g_phist[tid];
        s_ws[tid] = v;
        __syncthreads();
        for (int off = 1; off < THREADS; off <<= 1) {
            int t = (tid >= off) ? s_ws[tid - off] : 0;
            __syncthreads(); s_ws[tid] += t; __syncthreads();
        }
        s_pstart[tid] = s_ws[tid] - v;
        if (tid == THREADS - 1) s_pstart[NCP] = s_ws[tid];
        __syncthreads();
    }
    for (int j = gtid; j < nmm; j += gstride) {
        float gx = model[3 * j], gy = model[3 * j + 1], gz = model[3 * j + 2];
        int c = (cellc(gx, ox, ihx, G) * G + cellc(gy, oy, ihy, G)) * G + cellc(gz, oz, ihz, G);
        int pos = s_mstart[c] + atomicAdd(&g_mcur[c], 1);
        g_ms[pos] = make_float4(gx, gy, gz, fmaf(gx, gx, fmaf(gy, gy, gz * gz)));
    }
    for (int i = gtid; i < ntot; i += gstride) {
        float4 P = g_pu[i];
        int c = (cellc(P.x, ox, ipx, GP) * GP + cellc(P.y, oy, ipy, GP)) * GP + cellc(P.z, oz, ipz, GP);
        int pos = s_pstart[c] + atomicAdd(&g_pcur[c], 1);
        g_ps[pos] = P;
        g_wt[pos] = g_puw[i];
    }
    grid_bar(&g_bar3, GRID);
    if (blockIdx.x == 0) {                            // reset hists (shadowed by D)
        for (int c = tid; c < NCM; c += THREADS) { g_mhist[c] = 0; g_mcur[c] = 0; }
        for (int c = tid; c < NCP; c += THREADS) { g_phist[c] = 0; g_pcur[c] = 0; }
    }

    // ============ Phase D: work-stolen pred cells ============
    for (;;) {
        if (tid == 0) s_cell = (int)atomicAdd(&g_wq, 1u);
        __syncthreads();
        int c = s_cell;
        if (c >= NCP) break;
        int p0 = s_pstart[c], p1 = s_pstart[c + 1];
        int pcnt = p1 - p0;
        float cellsum = 0.0f;
        int nbatch = (pcnt + 127) >> 7;
        for (int b = 0; b < nbatch; b++) {
            int pb0 = p0 + b * 128;
            // ---- load preds, pack q ----
            float a[4], wgt[4];
            uint64_t qx2[4], qy2[4], qz2[4];
            #pragma unroll
            for (int k = 0; k < 4; k++) {
                int i = pb0 + k * 32 + lane;
                float qx = 0.f, qy = 0.f, qz = 0.f;
                a[k] = 0.f; wgt[k] = 0.f;
                if (i < p1) {
                    float4 P = g_ps[i];
                    qx = -2.0f * P.x; qy = -2.0f * P.y; qz = -2.0f * P.z;
                    a[k] = P.w; wgt[k] = g_wt[i];
                }
                asm("mov.b64 %0, {%1,%1};" : "=l"(qx2[k]) : "f"(qx));
                asm("mov.b64 %0, {%1,%1};" : "=l"(qy2[k]) : "f"(qy));
                asm("mov.b64 %0, {%1,%1};" : "=l"(qz2[k]) : "f"(qz));
            }
            // ---- batch AABB (warp 0) -> initial box (cells +-1) ----
            if (warp == 0) {
                float lx = FLT_MAX, ly = FLT_MAX, lz = FLT_MAX;
                float hxv = -FLT_MAX, hyv = -FLT_MAX, hzv = -FLT_MAX;
                #pragma unroll
                for (int k = 0; k < 4; k++) {
                    int i = pb0 + k * 32 + lane;
                    if (i < p1) {
                        float4 P = g_ps[i];
                        lx = fminf(lx, P.x); hxv = fmaxf(hxv, P.x);
                        ly = fminf(ly, P.y); hyv = fmaxf(hyv, P.y);
                        lz = fminf(lz, P.z); hzv = fmaxf(hzv, P.z);
                    }
                }
                #pragma unroll
                for (int o = 16; o > 0; o >>= 1) {
                    lx = fminf(lx, __shfl_xor_sync(0xffffffffu, lx, o));
                    ly = fminf(ly, __shfl_xor_sync(0xffffffffu, ly, o));
                    lz = fminf(lz, __shfl_xor_sync(0xffffffffu, lz, o));
                    hxv = fmaxf(hxv, __shfl_xor_sync(0xffffffffu, hxv, o));
                    hyv = fmaxf(hyv, __shfl_xor_sync(0xffffffffu, hyv, o));
                    hzv = fmaxf(hzv, __shfl_xor_sync(0xffffffffu, hzv, o));
                }
                if (lane == 0) {
                    s_bx[0] = max(cellc(lx, ox, ihx, G) - 1, 0);
                    s_bx[1] = min(cellc(hxv, ox, ihx, G) + 1, G - 1);
                    s_bx[2] = max(cellc(ly, oy, ihy, G) - 1, 0);
                    s_bx[3] = min(cellc(hyv, oy, ihy, G) + 1, G - 1);
                    s_bx[4] = max(cellc(lz, oz, ihz, G) - 1, 0);
                    s_bx[5] = min(cellc(hzv, oz, ihz, G) + 1, G - 1);
                }
            }
            __syncthreads();

            float m_lo[4], m_hi[4];
            #pragma unroll
            for (int k = 0; k < 4; k++) { m_lo[k] = 3.0e37f; m_hi[k] = 3.0e37f; }

            // ---- stage 1: expand box until >= target points, gather+scan ----
            for (;;) {
                if (warp == 0) {     // build segment tables
                    int bx0 = s_bx[0], bx1 = s_bx[1], by0 = s_bx[2], by1 = s_bx[3];
                    int bz0 = s_bx[4], bz1 = s_bx[5];
                    int ny = by1 - by0 + 1;
                    int nseg = (bx1 - bx0 + 1) * ny;
                    int cnts[8]; int base = lane * 8; int mysum = 0;
                    #pragma unroll
                    for (int r = 0; r < 8; r++) {
                        int s = base + r; int cv = 0;
                        if (s < nseg) {
                            int x = bx0 + s / ny, y = by0 + s % ny;
                            int row = (x * G + y) * G;
                            int st = s_mstart[row + bz0];
                            cv = s_mstart[row + bz1 + 1] - st;
                            s_segst[s] = st;
                        }
                        cnts[r] = cv; mysum += cv;
                    }
                    int incl = mysum;
                    #pragma unroll
                    for (int o = 1; o < 32; o <<= 1) {
                        int v = __shfl_up_sync(0xffffffffu, incl, o);
                        if (lane >= o) incl += v;
                    }
                    int run = incl - mysum;
                    #pragma unroll
                    for (int r = 0; r < 8; r++) {
                        int s = base + r;
                        if (s <= nseg && s < 256) s_segoff[s] = run;
                        run += cnts[r];
                    }
                    if (lane == 31) { s_segoff[256] = incl; s_total = incl; s_nseg = nseg; }
                    if (lane == 0 && nseg < 256) s_segoff[nseg] = s_segoff[nseg]; // no-op
                }
                __syncthreads();
                // ensure s_segoff[nseg] correct when nseg < 256 handled by owner lane above
                bool full = (s_bx[0] == 0 && s_bx[2] == 0 && s_bx[4] == 0 &&
                             s_bx[1] == G - 1 && s_bx[3] == G - 1 && s_bx[5] == G - 1);
                if (s_total >= target || full) break;
                if (tid == 0) {
                    s_bx[0] = max(s_bx[0] - 1, 0); s_bx[1] = min(s_bx[1] + 1, G - 1);
                    s_bx[2] = max(s_bx[2] - 1, 0); s_bx[3] = min(s_bx[3] + 1, G - 1);
                    s_bx[4] = max(s_bx[4] - 1, 0); s_bx[5] = min(s_bx[5] + 1, G - 1);
                }
                __syncthreads();
            }
            {
                int total = s_total, nseg = s_nseg;
                for (int cb = 0; cb < total; cb += BUFPTS) {
                    int cnt = min(BUFPTS, total - cb);
                    for (int t = tid; t < cnt; t += THREADS) {
                        int gi = cb + t;
                        int s = 0;
                        #pragma unroll
                        for (int st = 256; st > 0; st >>= 1)
                            if (s + st <= nseg && s_segoff[s + st] <= gi) s += st;
                        int idx = s_segst[s] + (gi - s_segoff[s]);
                        float4 gm = g_ms[idx];
                        int pp = t >> 1, oo = t & 1;
                        s_buf[pp * 8 + 0 + oo] = gm.x;
                        s_buf[pp * 8 + 2 + oo] = gm.y;
                        s_buf[pp * 8 + 4 + oo] = gm.z;
                        s_buf[pp * 8 + 6 + oo] = gm.w;
                    }
                    if ((cnt & 1) && tid == 0) {
                        int pp = cnt >> 1;
                        s_buf[pp * 8 + 1] = 0.f; s_buf[pp * 8 + 3] = 0.f;
                        s_buf[pp * 8 + 5] = 0.f; s_buf[pp * 8 + 7] = 3.0e37f;
                    }
                    __syncthreads();
                    scan_pairs(s_buf, (cnt + 1) >> 1, warp, qx2, qy2, qz2, m_lo, m_hi);
                    __syncthreads();
                }
            }
            #pragma unroll
            for (int k = 0; k < 4; k++)
                s_min[warp * 128 + k * 32 + lane] = fminf(m_lo[k], m_hi[k]);
            __syncthreads();
            // ---- reduce + per-pred W + union box (warp 0) ----
            if (warp == 0) {
                float ulx = FLT_MAX, uly = FLT_MAX, ulz = FLT_MAX;
                float uhx = -FLT_MAX, uhy = -FLT_MAX, uhz = -FLT_MAX;
                #pragma unroll
                for (int k = 0; k < 4; k++) {
                    int pidx = k * 32 + lane;
                    float m = s_min[pidx];
                    #pragma unroll
                    for (int s = 1; s < NWARP; s++) m = fminf(m, s_min[s * 128 + pidx]);
                    s_m1[pidx] = m;
                    int i = pb0 + pidx;
                    if (i < p1) {
                        float4 P = g_ps[i];
                        float W = sqrtf(fmaxf(a[k] + m, 0.f)) * 1.002f + 1e-6f;
                        ulx = fminf(ulx, P.x - W); uhx = fmaxf(uhx, P.x + W);
                        uly = fminf(uly, P.y - W); uhy = fmaxf(uhy, P.y + W);
                        ulz = fminf(ulz, P.z - W); uhz = fmaxf(uhz, P.z + W);
                    }
                }
                #pragma unroll
                for (int o = 16; o > 0; o >>= 1) {
                    ulx = fminf(ulx, __shfl_xor_sync(0xffffffffu, ulx, o));
                    uly = fminf(uly, __shfl_xor_sync(0xffffffffu, uly, o));
                    ulz = fminf(ulz, __shfl_xor_sync(0xffffffffu, ulz, o));
                    uhx = fmaxf(uhx, __shfl_xor_sync(0xffffffffu, uhx, o));
                    uhy = fmaxf(uhy, __shfl_xor_sync(0xffffffffu, uhy, o));
                    uhz = fmaxf(uhz, __shfl_xor_sync(0xffffffffu, uhz, o));
                }
                if (lane == 0) {
                    s_fb[0] = ulx; s_fb[1] = uhx; s_fb[2] = uly;
                    s_fb[3] = uhy; s_fb[4] = ulz; s_fb[5] = uhz;
                }
            }
            __syncthreads();
            if (tid == 0) {
                int b2[6];
                b2[0] = cellc(s_fb[0], ox, ihx, G); b2[1] = cellc(s_fb[1], ox, ihx, G);
                b2[2] = cellc(s_fb[2], oy, ihy, G); b2[3] = cellc(s_fb[3], oy, ihy, G);
                b2[4] = cellc(s_fb[4], oz, ihz, G); b2[5] = cellc(s_fb[5], oz, ihz, G);
                int skip = (b2[0] >= s_bx[0] && b2[1] <= s_bx[1] &&
                            b2[2] >= s_bx[2] && b2[3] <= s_bx[3] &&
                            b2[4] >= s_bx[4] && b2[5] <= s_bx[5]);
                s_skip = skip;
                if (!skip) {
                    #pragma unroll
                    for (int d = 0; d < 6; d++) s_bx[d] = b2[d];
                }
            }
            __syncthreads();
            // ---- stage 2: scan union box seeded (if it escapes stage-1 box) ----
            if (!s_skip) {
                if (warp == 0) {     // rebuild segments for box2
                    int bx0 = s_bx[0], bx1 = s_bx[1], by0 = s_bx[2], by1 = s_bx[3];
                    int bz0 = s_bx[4], bz1 = s_bx[5];
                    int ny = by1 - by0 + 1;
                    int nseg = (bx1 - bx0 + 1) * ny;
                    int cnts[8]; int base = lane * 8; int mysum = 0;
                    #pragma unroll
                    for (int r = 0; r < 8; r++) {
                        int s = base + r; int cv = 0;
                        if (s < nseg) {
                            int x = bx0 + s / ny, y = by0 + s % ny;
                            int row = (x * G + y) * G;
                            int st = s_mstart[row + bz0];
                            cv = s_mstart[row + bz1 + 1] - st;
                            s_segst[s] = st;
                        }
                        cnts[r] = cv; mysum += cv;
                    }
                    int incl = mysum;
                    #pragma unroll
                    for (int o = 1; o < 32; o <<= 1) {
                        int v = __shfl_up_sync(0xffffffffu, incl, o);
                        if (lane >= o) incl += v;
                    }
                    int run = incl - mysum;
                    #pragma unroll
                    for (int r = 0; r < 8; r++) {
                        int s = base + r;
                        if (s <= nseg && s < 256) s_segoff[s] = run;
                        run += cnts[r];
                    }
                    if (lane == 31) { s_segoff[256] = incl; s_total = incl; s_nseg = nseg; }
                }
                __syncthreads();
                float n_lo[4], n_hi[4];
                #pragma unroll
                for (int k = 0; k < 4; k++) { n_lo[k] = s_m1[k * 32 + lane]; n_hi[k] = 3.0e37f; }
                int total = s_total, nseg = s_nseg;
                for (int cb = 0; cb < total; cb += BUFPTS) {
                    int cnt = min(BUFPTS, total - cb);
                    for (int t = tid; t < cnt; t += THREADS) {
                        int gi = cb + t;
                        int s = 0;
                        #pragma unroll
                        for (int st = 256; st > 0; st >>= 1)
                            if (s + st <= nseg && s_segoff[s + st] <= gi) s += st;
                        int idx = s_segst[s] + (gi - s_segoff[s]);
                        float4 gm = g_ms[idx];
                        int pp = t >> 1, oo = t & 1;
                        s_buf[pp * 8 + 0 + oo] = gm.x;
                        s_buf[pp * 8 + 2 + oo] = gm.y;
                        s_buf[pp * 8 + 4 + oo] = gm.z;
                        s_buf[pp * 8 + 6 + oo] = gm.w;
                    }
                    if ((cnt & 1) && tid == 0) {
                        int pp = cnt >> 1;
                        s_buf[pp * 8 + 1] = 0.f; s_buf[pp * 8 + 3] = 0.f;
                        s_buf[pp * 8 + 5] = 0.f; s_buf[pp * 8 + 7] = 3.0e37f;
                    }
                    __syncthreads();
                    scan_pairs(s_buf, (cnt + 1) >> 1, warp, qx2, qy2, qz2, n_lo, n_hi);
                    __syncthreads();
                }
                #pragma unroll
                for (int k = 0; k < 4; k++)
                    s_min[warp * 128 + k * 32 + lane] = fminf(n_lo[k], n_hi[k]);
                __syncthreads();
                if (warp == 0) {
                    #pragma unroll
                    for (int k = 0; k < 4; k++) {
                        int pidx = k * 32 + lane;
                        float m = s_min[pidx];
                        #pragma unroll
                        for (int s = 1; s < NWARP; s++) m = fminf(m, s_min[s * 128 + pidx]);
                        s_m1[pidx] = m;
                    }
                }
                __syncthreads();
            }
            // ---- batch weighted sum (warp 0) ----
            if (warp == 0) {
                float v = 0.0f;
                #pragma unroll
                for (int k = 0; k < 4; k++) {
                    int pidx = k * 32 + lane;
                    if (pb0 + pidx < p1) v += (a[k] + s_m1[pidx]) * wgt[k];
                }
                #pragma unroll
                for (int o = 16; o > 0; o >>= 1)
                    v += __shfl_down_sync(0xffffffffu, v, o);
                if (lane == 0) cellsum += v;
            }
            __syncthreads();
        }
        if (warp == 0 && lane == 0) g_partials[c] = cellsum;
        __syncthreads();
    }

    // ============ final fixed-order reduction ============
    if (tid == 0) {
        __threadfence();
        unsigned int t = atomicAdd(&g_ticket, 1u);
        s_last = (t == GRID - 1u) ? 1 : 0;
    }
    __syncthreads();
    if (s_last && warp == 0) {
        float s = 0.0f;
        for (int b = lane; b < NCP; b += 32)
            s += *((volatile float*)&g_partials[b]);
        #pragma unroll
        for (int o = 16; o > 0; o >>= 1)
            s += __shfl_down_sync(0xffffffffu, s, o);
        if (lane == 0) {
            out[0] = s;
            g_ticket = 0; g_bar1 = 0; g_bar2 = 0; g_bar3 = 0; g_wq = 0;
        }
    }
}

extern "C" void kernel_launch(void* const* d_in, const int* in_sizes, int n_in,
                              void* d_out, int out_size) {
    const float* vis   = (const float*)d_in[0];  // visual_points  (16384,3)
    const float* tac   = (const float*)d_in[1];  // tactile_points (2048,3)
    const float* model = (const float*)d_in[2];  // model_points   (8192,3)
    const float* scale = (const float*)d_in[3];  // scalar
    const float* state = (const float*)d_in[4];  // (6,)
    float* out = (float*)d_out;

    int nv = in_sizes[0] / 3;
    int nt = in_sizes[1] / 3;
    int nm = in_sizes[2] / 3;

    int grid = 144;   // all-resident (1 CTA/SM at this smem size) for barriers

    cudaFuncSetAttribute(cd_kernel, cudaFuncAttributeMaxDynamicSharedMemorySize,
                         SMEM_TOTAL);

    float wv = 1.0f / (float)nv;
    float wt = 0.1f / (float)nt;

    cd_kernel<<<grid, THREADS, SMEM_TOTAL>>>(vis, tac, model, scale, state, out,
                                             nv, nt, nm, wv, wt);
}

// round 13
// speedup vs baseline: 2.2187x; 2.2187x over previous
#include <cuda_runtime.h>
#include <math.h>
#include <cstdint>
#include <float.h>

#define THREADS  512
#define NWARPS   16
#define PAIRS    8                         // model pairs per lane (16 points)
#define PRED_CTA 128
#define CHUNK    (NWARPS * 32 * PAIRS * 2) // 8192 points per chunk
#define NB_MAX   256
#define BIGF     3.0e37f

__device__ float g_partials[NB_MAX];
__device__ unsigned int g_ticket;   // zero-init; last CTA resets each launch

__global__ __launch_bounds__(THREADS, 1)
void cd_kernel(const float* __restrict__ vis,
               const float* __restrict__ tac,
               const float* __restrict__ model,
               const float* __restrict__ scale,
               const float* __restrict__ state,
               float* __restrict__ out,
               int nv, int nt, int nm,
               float wv, float wt, int nbp) {
    __shared__ float  s_par[13];
    __shared__ float4 s_q1[PRED_CTA];           // (qx,qx,qy,qy) pre-duplicated
    __shared__ float2 s_q2[PRED_CTA];           // (qz,qz)
    __shared__ float2 s_aw[PRED_CTA];           // (a, weight)
    __shared__ float  s_wm[PRED_CTA * NWARPS];  // per (pred, warp) min
    __shared__ float  s_red[4];
    __shared__ int    s_last;

    const int tid  = threadIdx.x;
    const int lane = tid & 31;
    const int warp = tid >> 5;
    const int ntot = nv + nt;

    // ---- transform params ----
    if (tid == 0) {
        float oxs = state[3], oys = state[4], ozs = state[5];
        float sx = sinf(oxs), cx = cosf(oxs);
        float sy = sinf(oys), cy = cosf(oys);
        float sz = sinf(ozs), cz = cosf(ozs);
        s_par[0] = cz * cy;
        s_par[1] = cz * sy * sx - sz * cx;
        s_par[2] = cz * sy * cx + sz * sx;
        s_par[3] = sz * cy;
        s_par[4] = sz * sy * sx + cz * cx;
        s_par[5] = sz * sy * cx - cz * sx;
        s_par[6] = -sy;
        s_par[7] = cy * sx;
        s_par[8] = cy * cx;
        s_par[9]  = state[0];
        s_par[10] = state[1];
        s_par[11] = state[2];
        s_par[12] = 1.0f / scale[0];
    }
    __syncthreads();

    uint32_t a1b, a2b;
    {
        uint64_t t64;
        asm("cvta.to.shared.u64 %0, %1;" : "=l"(t64) : "l"(s_q1));
        a1b = (uint32_t)t64;
        asm("cvta.to.shared.u64 %0, %1;" : "=l"(t64) : "l"(s_q2));
        a2b = (uint32_t)t64;
    }

    const int nchunk = (nm + CHUNK - 1) / CHUNK;
    float ctasum = 0.0f;

    for (int pb = blockIdx.x; pb < nbp; pb += gridDim.x) {
        // ---- stage this block's 128 preds ----
        if (tid < PRED_CTA) {
            int i = pb * PRED_CTA + tid;
            float qx = 0.f, qy = 0.f, qz = 0.f, a = 0.f, w = 0.f;
            if (i < ntot) {
                const float* src; int idx;
                if (i < nv) { src = vis; idx = i;      w = wv; }
                else        { src = tac; idx = i - nv; w = wt; }
                float vx = src[3 * idx + 0] - s_par[9];
                float vy = src[3 * idx + 1] - s_par[10];
                float vz = src[3 * idx + 2] - s_par[11];
                float inv_s = s_par[12];
                float px = (vx * s_par[0] + vy * s_par[3] + vz * s_par[6]) * inv_s;
                float py = (vx * s_par[1] + vy * s_par[4] + vz * s_par[7]) * inv_s;
                float pz = (vx * s_par[2] + vy * s_par[5] + vz * s_par[8]) * inv_s;
                a = fmaf(px, px, fmaf(py, py, pz * pz));
                qx = -2.0f * px; qy = -2.0f * py; qz = -2.0f * pz;
            }
            s_q1[tid] = make_float4(qx, qx, qy, qy);
            s_q2[tid] = make_float2(qz, qz);
            s_aw[tid] = make_float2(a, w);
        }
        for (int t = tid; t < PRED_CTA * NWARPS; t += THREADS) s_wm[t] = BIGF;
        __syncthreads();

        for (int ch = 0; ch < nchunk; ch++) {
            // ---- load this lane's 8 point-pairs into registers ----
            uint64_t Px[PAIRS], Py[PAIRS], Pz[PAIRS], Pw[PAIRS];
            #pragma unroll
            for (int p = 0; p < PAIRS; p++) {
                int pr = ch * (CHUNK / 2) + warp * (32 * PAIRS) + p * 32 + lane;
                int j0 = pr * 2, j1 = pr * 2 + 1;
                float x0 = 0.f, y0 = 0.f, z0 = 0.f, w0 = BIGF;
                float x1 = 0.f, y1 = 0.f, z1 = 0.f, w1 = BIGF;
                if (j0 < nm) {
                    x0 = model[3 * j0]; y0 = model[3 * j0 + 1]; z0 = model[3 * j0 + 2];
                    w0 = fmaf(x0, x0, fmaf(y0, y0, z0 * z0));
                }
                if (j1 < nm) {
                    x1 = model[3 * j1]; y1 = model[3 * j1 + 1]; z1 = model[3 * j1 + 2];
                    w1 = fmaf(x1, x1, fmaf(y1, y1, z1 * z1));
                }
                asm("mov.b64 %0, {%1,%2};" : "=l"(Px[p]) : "f"(x0), "f"(x1));
                asm("mov.b64 %0, {%1,%2};" : "=l"(Py[p]) : "f"(y0), "f"(y1));
                asm("mov.b64 %0, {%1,%2};" : "=l"(Pz[p]) : "f"(z0), "f"(z1));
                asm("mov.b64 %0, {%1,%2};" : "=l"(Pw[p]) : "f"(w0), "f"(w1));
            }

            // ---- stream preds: 2 per step, every warp covers all 128 ----
            for (int j = 0; j < PRED_CTA; j += 2) {
                uint64_t qxA, qyA, qzA, qxB, qyB, qzB;
                asm("ld.shared.v2.u64 {%0,%1}, [%2];"
                    : "=l"(qxA), "=l"(qyA) : "r"(a1b + (uint32_t)j * 16u));
                asm("ld.shared.b64 %0, [%1];"
                    : "=l"(qzA) : "r"(a2b + (uint32_t)j * 8u));
                asm("ld.shared.v2.u64 {%0,%1}, [%2];"
                    : "=l"(qxB), "=l"(qyB) : "r"(a1b + (uint32_t)j * 16u + 16u));
                asm("ld.shared.b64 %0, [%1];"
                    : "=l"(qzB) : "r"(a2b + (uint32_t)j * 8u + 8u));

                float loA = BIGF, hiA = BIGF, loB = BIGF, hiB = BIGF;
                #pragma unroll
                for (int p = 0; p < PAIRS; p++) {
                    uint64_t dA, dB;
                    asm("fma.rn.f32x2 %0, %1, %2, %3;" : "=l"(dA)
                        : "l"(qzA), "l"(Pz[p]), "l"(Pw[p]));
                    asm("fma.rn.f32x2 %0, %1, %2, %3;" : "=l"(dB)
                        : "l"(qzB), "l"(Pz[p]), "l"(Pw[p]));
                    asm("fma.rn.f32x2 %0, %1, %2, %0;" : "+l"(dA)
                        : "l"(qyA), "l"(Py[p]));
                    asm("fma.rn.f32x2 %0, %1, %2, %0;" : "+l"(dB)
                        : "l"(qyB), "l"(Py[p]));
                    asm("fma.rn.f32x2 %0, %1, %2, %0;" : "+l"(dA)
                        : "l"(qxA), "l"(Px[p]));
                    asm("fma.rn.f32x2 %0, %1, %2, %0;" : "+l"(dB)
                        : "l"(qxB), "l"(Px[p]));
                    float al, ah, bl, bh;
                    asm("mov.b64 {%0,%1}, %2;" : "=f"(al), "=f"(ah) : "l"(dA));
                    asm("mov.b64 {%0,%1}, %2;" : "=f"(bl), "=f"(bh) : "l"(dB));
                    loA = fminf(loA, al); hiA = fminf(hiA, ah);
                    loB = fminf(loB, bl); hiB = fminf(hiB, bh);
                }
                float mA = fminf(loA, hiA);
                float mB = fminf(loB, hiB);
                #pragma unroll
                for (int o = 16; o > 0; o >>= 1) {
                    mA = fminf(mA, __shfl_xor_sync(0xffffffffu, mA, o));
                    mB = fminf(mB, __shfl_xor_sync(0xffffffffu, mB, o));
                }
                if (lane == 0) {
                    int b0 = j * NWARPS + warp;
                    int b1 = (j + 1) * NWARPS + warp;
                    s_wm[b0] = fminf(s_wm[b0], mA);
                    s_wm[b1] = fminf(s_wm[b1], mB);
                }
            }
        }
        __syncthreads();

        // ---- block combine ----
        float vsum = 0.0f;
        if (tid < PRED_CTA) {
            float m = s_wm[tid * NWARPS];
            #pragma unroll
            for (int w2 = 1; w2 < NWARPS; w2++)
                m = fminf(m, s_wm[tid * NWARPS + w2]);
            float2 aw = s_aw[tid];
            vsum = (aw.x + m) * aw.y;
        }
        #pragma unroll
        for (int o = 16; o > 0; o >>= 1)
            vsum += __shfl_down_sync(0xffffffffu, vsum, o);
        if (lane == 0 && warp < 4) s_red[warp] = vsum;
        __syncthreads();
        if (tid == 0) ctasum += (s_red[0] + s_red[1]) + (s_red[2] + s_red[3]);
        __syncthreads();
    }
    if (tid == 0) g_partials[blockIdx.x] = ctasum;

    // ---- last-CTA fused final reduction ----
    if (tid == 0) {
        __threadfence();
        unsigned int t = atomicAdd(&g_ticket, 1u);
        s_last = (t == gridDim.x - 1u) ? 1 : 0;
    }
    __syncthreads();
    if (s_last && warp == 0) {
        float s = 0.0f;
        for (int b = lane; b < (int)gridDim.x; b += 32)
            s += *((volatile float*)&g_partials[b]);
        #pragma unroll
        for (int o = 16; o > 0; o >>= 1)
            s += __shfl_down_sync(0xffffffffu, s, o);
        if (lane == 0) {
            out[0] = s;
            g_ticket = 0;   // reset for next graph replay
        }
    }
}

extern "C" void kernel_launch(void* const* d_in, const int* in_sizes, int n_in,
                              void* d_out, int out_size) {
    const float* vis   = (const float*)d_in[0];  // visual_points  (16384,3)
    const float* tac   = (const float*)d_in[1];  // tactile_points (2048,3)
    const float* model = (const float*)d_in[2];  // model_points   (8192,3)
    const float* scale = (const float*)d_in[3];  // scalar
    const float* state = (const float*)d_in[4];  // (6,)
    float* out = (float*)d_out;

    int nv = in_sizes[0] / 3;
    int nt = in_sizes[1] / 3;
    int nm = in_sizes[2] / 3;

    int ntot = nv + nt;
    int nbp = (ntot + PRED_CTA - 1) / PRED_CTA;   // 144 for default shapes
    int grid = nbp < 148 ? nbp : 148;             // partials bounded by grid

    float wv = 1.0f / (float)nv;
    float wt = 0.1f / (float)nt;

    cd_kernel<<<grid, THREADS>>>(vis, tac, model, scale, state, out,
                                 nv, nt, nm, wv, wt, nbp);
}

// round 14
// speedup vs baseline: 2.5282x; 1.1395x over previous
#include <cuda_runtime.h>
#include <math.h>
#include <cstdint>
#include <float.h>

#define NBIN     512
#define BINSCALE 64.0f
#define THREADS  512
#define NWARP    16
#define NB_MAX   256
#define MAXM     16384
#define MAXP     32768
#define SLABPAIRS 1024          // 2048-point slab
#define BIGF     3.0e37f

// -------- device scratch (static; no allocations) --------
__device__ float  g_msp[(MAXM / 2 + 1) * 8];   // norm-sorted model, pair-interleaved
__device__ float4 g_pu[MAXP];                  // unsorted preds (px,py,pz,a)
__device__ float  g_puw[MAXP];
__device__ float4 g_ps[MAXP];                  // norm-sorted preds
__device__ float  g_psw[MAXP];
__device__ int g_mhist[NBIN], g_phist[NBIN], g_mcur[NBIN], g_pcur[NBIN];
__device__ float g_partials[NB_MAX];
__device__ unsigned int g_bar1, g_bar2, g_ticket;

__device__ __forceinline__ int norm_bin(float r) {
    int b = (int)(r * BINSCALE);
    if (b < 0) b = 0;
    if (b > NBIN - 1) b = NBIN - 1;
    return b;
}

__device__ __forceinline__ void grid_bar(unsigned int* ctr, unsigned int tgt) {
    __syncthreads();
    if (threadIdx.x == 0) {
        __threadfence();
        atomicAdd(ctr, 1u);
        while (*((volatile unsigned int*)ctr) < tgt) { }
        __threadfence();
    }
    __syncthreads();
}

// packed f32x2 distance+min for one pair record (x2,y2,z2,w2 already loaded)
#define PAIRM(X2, Y2, Z2, W2)                                                  \
    {                                                                          \
        _Pragma("unroll")                                                      \
        for (int k = 0; k < 4; k++) {                                          \
            uint64_t d2;                                                       \
            asm("fma.rn.f32x2 %0, %1, %2, %3;" : "=l"(d2)                      \
                : "l"(qz2[k]), "l"(Z2), "l"(W2));                              \
            asm("fma.rn.f32x2 %0, %1, %2, %0;" : "+l"(d2)                      \
                : "l"(qy2[k]), "l"(Y2));                                       \
            asm("fma.rn.f32x2 %0, %1, %2, %0;" : "+l"(d2)                      \
                : "l"(qx2[k]), "l"(X2));                                       \
            float dlo, dhi;                                                    \
            asm("mov.b64 {%0,%1}, %2;" : "=f"(dlo), "=f"(dhi) : "l"(d2));      \
            m_lo[k] = fminf(m_lo[k], dlo);                                     \
            m_hi[k] = fminf(m_hi[k], dhi);                                     \
        }                                                                      \
    }

#define LDG_PAIR(X2, Y2, Z2, W2, GP)                                           \
    asm("ld.global.nc.v2.u64 {%0,%1}, [%2];"                                   \
        : "=l"(X2), "=l"(Y2) : "l"(GP));                                       \
    asm("ld.global.nc.v2.u64 {%0,%1}, [%2+16];"                                \
        : "=l"(Z2), "=l"(W2) : "l"(GP));

__global__ __launch_bounds__(THREADS, 1)
void cd_kernel(const float* __restrict__ vis,
               const float* __restrict__ tac,
               const float* __restrict__ model,
               const float* __restrict__ scale,
               const float* __restrict__ state,
               float* __restrict__ out,
               int nv, int nt, int nm,
               float wv, float wt, int nbp) {
    __shared__ float s_par[13];
    __shared__ float s_min[NWARP * 128];
    __shared__ float s_m1[128];
    __shared__ int s_mstart[NBIN + 1];
    __shared__ int s_pstart[NBIN + 1];
    __shared__ int s_wsum[NWARP];
    __shared__ int s_wlo_i, s_whi_i, s_slab0, s_sp, s_n1, s_n2, s_last;

    const int tid  = threadIdx.x;
    const int lane = tid & 31;
    const int warp = tid >> 5;
    const int ntot0 = nv + nt;
    const int ntot = ntot0 < MAXP ? ntot0 : MAXP;
    const int nmm  = nm < MAXM ? nm : MAXM;
    const int npair = (nmm + 1) >> 1;
    const unsigned int GRID = gridDim.x;
    const int gstride = (int)GRID * THREADS;
    const int gtid = blockIdx.x * THREADS + tid;

    // ---- transform params ----
    if (tid == 0) {
        float oxs = state[3], oys = state[4], ozs = state[5];
        float sx = sinf(oxs), cx = cosf(oxs);
        float sy = sinf(oys), cy = cosf(oys);
        float sz = sinf(ozs), cz = cosf(ozs);
        s_par[0] = cz * cy;
        s_par[1] = cz * sy * sx - sz * cx;
        s_par[2] = cz * sy * cx + sz * sx;
        s_par[3] = sz * cy;
        s_par[4] = sz * sy * sx + cz * cx;
        s_par[5] = sz * sy * cx - cz * sx;
        s_par[6] = -sy;
        s_par[7] = cy * sx;
        s_par[8] = cy * cx;
        s_par[9]  = state[0];
        s_par[10] = state[1];
        s_par[11] = state[2];
        s_par[12] = 1.0f / scale[0];
    }
    __syncthreads();

    // ============ Phase A: histograms + pred transform ============
    for (int j = gtid; j < nmm; j += gstride) {
        float gx = model[3 * j], gy = model[3 * j + 1], gz = model[3 * j + 2];
        float b = fmaf(gx, gx, fmaf(gy, gy, gz * gz));
        atomicAdd(&g_mhist[norm_bin(sqrtf(b))], 1);
    }
    for (int i = gtid; i < ntot; i += gstride) {
        const float* src; int idx; float w;
        if (i < nv) { src = vis; idx = i;      w = wv; }
        else        { src = tac; idx = i - nv; w = wt; }
        float vx = src[3 * idx + 0] - s_par[9];
        float vy = src[3 * idx + 1] - s_par[10];
        float vz = src[3 * idx + 2] - s_par[11];
        float inv_s = s_par[12];
        float px = (vx * s_par[0] + vy * s_par[3] + vz * s_par[6]) * inv_s;
        float py = (vx * s_par[1] + vy * s_par[4] + vz * s_par[7]) * inv_s;
        float pz = (vx * s_par[2] + vy * s_par[5] + vz * s_par[8]) * inv_s;
        float a = fmaf(px, px, fmaf(py, py, pz * pz));
        g_pu[i]  = make_float4(px, py, pz, a);
        g_puw[i] = w;
        atomicAdd(&g_phist[norm_bin(sqrtf(a))], 1);
    }
    grid_bar(&g_bar1, GRID);

    // ============ Phase B: warp-shfl prefix scans (every CTA) ============
    {
        // model bins (NBIN == THREADS)
        int v = g_mhist[tid];
        int incl = v;
        #pragma unroll
        for (int o = 1; o < 32; o <<= 1) {
            int t = __shfl_up_sync(0xffffffffu, incl, o);
            if (lane >= o) incl += t;
        }
        if (lane == 31) s_wsum[warp] = incl;
        __syncthreads();
        if (warp == 0) {
            int wvv = (lane < NWARP) ? s_wsum[lane] : 0;
            int wi = wvv;
            #pragma unroll
            for (int o = 1; o < 16; o <<= 1) {
                int t = __shfl_up_sync(0xffffffffu, wi, o);
                if (lane >= o) wi += t;
            }
            if (lane < NWARP) s_wsum[lane] = wi - wvv;
        }
        __syncthreads();
        s_mstart[tid] = incl - v + s_wsum[warp];
        if (tid == THREADS - 1) s_mstart[NBIN] = incl + s_wsum[warp];
        __syncthreads();

        // pred bins
        int v2 = g_phist[tid];
        int incl2 = v2;
        #pragma unroll
        for (int o = 1; o < 32; o <<= 1) {
            int t = __shfl_up_sync(0xffffffffu, incl2, o);
            if (lane >= o) incl2 += t;
        }
        if (lane == 31) s_wsum[warp] = incl2;
        __syncthreads();
        if (warp == 0) {
            int wvv = (lane < NWARP) ? s_wsum[lane] : 0;
            int wi = wvv;
            #pragma unroll
            for (int o = 1; o < 16; o <<= 1) {
                int t = __shfl_up_sync(0xffffffffu, wi, o);
                if (lane >= o) wi += t;
            }
            if (lane < NWARP) s_wsum[lane] = wi - wvv;
        }
        __syncthreads();
        s_pstart[tid] = incl2 - v2 + s_wsum[warp];
        if (tid == THREADS - 1) s_pstart[NBIN] = incl2 + s_wsum[warp];
        __syncthreads();
    }

    // ============ Phase C: scatter into norm order ============
    for (int j = gtid; j < nmm; j += gstride) {
        float gx = model[3 * j], gy = model[3 * j + 1], gz = model[3 * j + 2];
        float b = fmaf(gx, gx, fmaf(gy, gy, gz * gz));
        int bn = norm_bin(sqrtf(b));
        int pos = s_mstart[bn] + atomicAdd(&g_mcur[bn], 1);
        float* r = g_msp + (size_t)(pos >> 1) * 8;
        int o = pos & 1;
        r[0 + o] = gx; r[2 + o] = gy; r[4 + o] = gz; r[6 + o] = b;
    }
    if ((nmm & 1) && gtid == 0) {          // pad odd tail
        float* r = g_msp + (size_t)(nmm >> 1) * 8;
        r[1] = 0.f; r[3] = 0.f; r[5] = 0.f; r[7] = BIGF;
    }
    for (int i = gtid; i < ntot; i += gstride) {
        float4 P = g_pu[i];
        int bn = norm_bin(sqrtf(P.w));
        int pos = s_pstart[bn] + atomicAdd(&g_pcur[bn], 1);
        g_ps[pos] = P;
        g_psw[pos] = g_puw[i];
    }
    grid_bar(&g_bar2, GRID);
    if (blockIdx.x == 0) {                 // reset for next replay (shadowed by D)
        g_mhist[tid] = 0; g_phist[tid] = 0; g_mcur[tid] = 0; g_pcur[tid] = 0;
    }

    // ============ Phase D: slab scan + residual, direct from global ============
    for (int pb = blockIdx.x; pb < nbp; pb += (int)GRID) {
        float a[4], wgt[4], rr[4];
        uint64_t qx2[4], qy2[4], qz2[4];
        #pragma unroll
        for (int k = 0; k < 4; k++) {
            int i = pb * 128 + k * 32 + lane;
            float qx = 0.f, qy = 0.f, qz = 0.f;
            a[k] = 0.f; wgt[k] = 0.f; rr[k] = 0.f;
            if (i < ntot) {
                float4 P = g_ps[i];
                qx = -2.0f * P.x; qy = -2.0f * P.y; qz = -2.0f * P.z;
                a[k] = P.w; wgt[k] = g_psw[i]; rr[k] = sqrtf(P.w);
            }
            asm("mov.b64 %0, {%1,%1};" : "=l"(qx2[k]) : "f"(qx));
            asm("mov.b64 %0, {%1,%1};" : "=l"(qy2[k]) : "f"(qy));
            asm("mov.b64 %0, {%1,%1};" : "=l"(qz2[k]) : "f"(qz));
        }
        if (tid == 0) {
            s_wlo_i = 0x7f7fffff;
            s_whi_i = 0;
            int imid = pb * 128 + 64; if (imid >= ntot) imid = ntot - 1;
            float rmid = sqrtf(g_ps[imid].w);
            int sp = npair < SLABPAIRS ? npair : SLABPAIRS;
            int s0 = (s_mstart[norm_bin(rmid)] >> 1) - sp / 2;
            if (s0 < 0) s0 = 0;
            if (s0 > npair - sp) s0 = npair - sp;
            s_slab0 = s0; s_sp = sp;
        }
        __syncthreads();

        // ---- stage 1: slab scan from global ----
        float m_lo[4], m_hi[4];
        #pragma unroll
        for (int k = 0; k < 4; k++) { m_lo[k] = BIGF; m_hi[k] = BIGF; }
        {
            int sp = s_sp;
            int per = (sp + NWARP - 1) / NWARP;
            int wb = s_slab0 + warp * per;
            int we = wb + per;
            int wend = s_slab0 + sp;
            if (we > wend) we = wend;
            const char* gp = (const char*)g_msp + (size_t)wb * 32;
            #pragma unroll 4
            for (int p = wb; p < we; ++p, gp += 32) {
                uint64_t x2, y2, z2, w2;
                LDG_PAIR(x2, y2, z2, w2, gp)
                PAIRM(x2, y2, z2, w2)
            }
        }
        #pragma unroll
        for (int k = 0; k < 4; k++)
            s_min[warp * 128 + k * 32 + lane] = fminf(m_lo[k], m_hi[k]);
        __syncthreads();

        // ---- reduce, per-pred window, union (warp 0) ----
        if (warp == 0) {
            #pragma unroll
            for (int k = 0; k < 4; k++) {
                int pidx = k * 32 + lane;
                float m = s_min[pidx];
                #pragma unroll
                for (int s = 1; s < NWARP; s++) m = fminf(m, s_min[s * 128 + pidx]);
                s_m1[pidx] = m;
                int i = pb * 128 + pidx;
                if (i < ntot) {
                    float W = sqrtf(fmaxf(a[k] + m, 0.f)) * 1.002f + 1e-5f;
                    float wlo = fmaxf(rr[k] - W, 0.f);
                    float whi = rr[k] + W;
                    atomicMin(&s_wlo_i, __float_as_int(wlo));
                    atomicMax(&s_whi_i, __float_as_int(whi));
                }
            }
        }
        __syncthreads();
        if (tid == 0) {
            float wlo = __int_as_float(s_wlo_i);
            float whi = __int_as_float(s_whi_i);
            int r0p = s_mstart[norm_bin(wlo)] >> 1;
            int r1p = (s_mstart[norm_bin(whi) + 1] + 1) >> 1;
            if (r1p > npair) r1p = npair;
            s_n1 = max(0, s_slab0 - r0p);
            s_n2 = max(0, r1p - (s_slab0 + s_sp));
        }
        __syncthreads();

        // ---- stage 2: residual ranges only (seeded) ----
        int nres = s_n1 + s_n2;
        if (nres > 0) {
            int n1 = s_n1;
            int lo0 = s_slab0 - n1;              // first missing-low pair
            int hi0 = s_slab0 + s_sp;            // first missing-high pair
            #pragma unroll
            for (int k = 0; k < 4; k++) { m_lo[k] = s_m1[k * 32 + lane]; m_hi[k] = BIGF; }
            int per = (nres + NWARP - 1) / NWARP;
            int wb = warp * per; if (wb > nres) wb = nres;
            int we = wb + per;   if (we > nres) we = nres;
            for (int i = wb; i < we; ++i) {
                int pidx = (i < n1) ? (lo0 + i) : (hi0 + (i - n1));
                const char* gp = (const char*)g_msp + (size_t)pidx * 32;
                uint64_t x2, y2, z2, w2;
                LDG_PAIR(x2, y2, z2, w2, gp)
                PAIRM(x2, y2, z2, w2)
            }
            #pragma unroll
            for (int k = 0; k < 4; k++)
                s_min[warp * 128 + k * 32 + lane] = fminf(m_lo[k], m_hi[k]);
            __syncthreads();
            if (warp == 0) {
                #pragma unroll
                for (int k = 0; k < 4; k++) {
                    int pidx = k * 32 + lane;
                    float m = s_min[pidx];
                    #pragma unroll
                    for (int s = 1; s < NWARP; s++) m = fminf(m, s_min[s * 128 + pidx]);
                    s_m1[pidx] = m;
                }
            }
            __syncthreads();
        }

        // ---- block-weighted sum ----
        if (warp == 0) {
            float vsum = 0.0f;
            #pragma unroll
            for (int k = 0; k < 4; k++) {
                int pidx = k * 32 + lane;
                if (pb * 128 + pidx < ntot) vsum += (a[k] + s_m1[pidx]) * wgt[k];
            }
            #pragma unroll
            for (int o = 16; o > 0; o >>= 1)
                vsum += __shfl_down_sync(0xffffffffu, vsum, o);
            if (lane == 0 && pb < NB_MAX) g_partials[pb] = vsum;
        }
        __syncthreads();
    }

    // ============ final fixed-order reduction ============
    if (tid == 0) {
        __threadfence();
        unsigned int t = atomicAdd(&g_ticket, 1u);
        s_last = (t == GRID - 1u) ? 1 : 0;
    }
    __syncthreads();
    if (s_last && warp == 0) {
        float s = 0.0f;
        for (int b = lane; b < nbp; b += 32)
            s += *((volatile float*)&g_partials[b]);
        #pragma unroll
        for (int o = 16; o > 0; o >>= 1)
            s += __shfl_down_sync(0xffffffffu, s, o);
        if (lane == 0) {
            out[0] = s;
            g_ticket = 0; g_bar1 = 0; g_bar2 = 0;   // reset for replay
        }
    }
}

extern "C" void kernel_launch(void* const* d_in, const int* in_sizes, int n_in,
                              void* d_out, int out_size) {
    const float* vis   = (const float*)d_in[0];  // visual_points  (16384,3)
    const float* tac   = (const float*)d_in[1];  // tactile_points (2048,3)
    const float* model = (const float*)d_in[2];  // model_points   (8192,3)
    const float* scale = (const float*)d_in[3];  // scalar
    const float* state = (const float*)d_in[4];  // (6,)
    float* out = (float*)d_out;

    int nv = in_sizes[0] / 3;
    int nt = in_sizes[1] / 3;
    int nm = in_sizes[2] / 3;

    int ntot = nv + nt;
    int nbp = (ntot + 127) / 128;               // 144 for default shapes
    if (nbp > NB_MAX) nbp = NB_MAX;
    int grid = nbp < 144 ? nbp : 144;           // all-resident for barriers

    float wv = 1.0f / (float)nv;
    float wt = 0.1f / (float)nt;

    cd_kernel<<<grid, THREADS>>>(vis, tac, model, scale, state, out,
                                 nv, nt, nm, wv, wt, nbp);
}